// round 11
// baseline (speedup 1.0000x reference)
#include <cuda_runtime.h>
#include <cuda_fp16.h>
#include <cstdint>

#define Nn 50000
#define Ee 800000
#define NEG 0.2f
#define NB_SCAN ((Nn + 255) / 256)

// ---------------- scratch (device globals; no runtime allocation) ----------
__device__ uint32_t g_xl16[(size_t)Nn * 64];   // xl in half2 pairs
__device__ uint32_t g_xr16[(size_t)Nn * 64];   // xr in half2 pairs
__device__ float    g_h[(size_t)Nn * 128];
__device__ float    g_lsum[Nn];
__device__ float    g_lattr[Nn];
__device__ int      g_cnt[Nn];
__device__ int      g_beg[Nn];
__device__ int      g_wp[Nn];
__device__ volatile unsigned g_scanstate[NB_SCAN];
__device__ int2     g_edge[Ee];                // (src, attr-bits)
__device__ uint32_t g_wtf[5 * 128 * 128];      // weights pre-converted to tf32 bits

#define AGG_READY    0x40000000u
#define PREFIX_READY 0x80000000u
#define VAL_MASK     0x3FFFFFFFu

// ---------------- helpers ---------------------------------------------------
__device__ __forceinline__ uint32_t to_tf32(float f) {
    uint32_t u;
    asm("cvt.rna.tf32.f32 %0, %1;" : "=r"(u) : "f"(f));
    return u;
}
__device__ __forceinline__ void cp16(void* s, const void* g, bool pred) {
    unsigned sa = (unsigned)__cvta_generic_to_shared(s);
    int sz = pred ? 16 : 0;
    asm volatile("cp.async.cg.shared.global [%0], [%1], 16, %2;\n"
                 :: "r"(sa), "l"(g), "r"(sz));
}
__device__ __forceinline__ void cp_commit() { asm volatile("cp.async.commit_group;\n"); }
__device__ __forceinline__ void cp_wait()   { asm volatile("cp.async.wait_group 0;\n"); }

__device__ __forceinline__ void mma_tf32(float c[4], uint32_t a0, uint32_t a1,
                                         uint32_t a2, uint32_t a3,
                                         uint32_t b0, uint32_t b1) {
    asm volatile(
        "mma.sync.aligned.m16n8k8.row.col.f32.tf32.tf32.f32 "
        "{%0,%1,%2,%3}, {%4,%5,%6,%7}, {%8,%9}, {%0,%1,%2,%3};\n"
        : "+f"(c[0]), "+f"(c[1]), "+f"(c[2]), "+f"(c[3])
        : "r"(a0), "r"(a1), "r"(a2), "r"(a3), "r"(b0), "r"(b1));
}
__device__ __forceinline__ __half2 lrelu2(__half2 v) {
    const __half2 z = __float2half2_rn(0.f);
    const __half2 c = __float2half2_rn(NEG);
    return __hfma2(c, __hmin2(v, z), __hmax2(v, z));
}

// ================= weight preconvert (once per launch) ======================
__global__ void cvtW_k(const float* __restrict__ w0, const float* __restrict__ w1,
                       const float* __restrict__ w2, const float* __restrict__ w3,
                       const float* __restrict__ w4) {
    int i = blockIdx.x * blockDim.x + threadIdx.x;
    if (i >= 5 * 16384) return;
    int slot = i >> 14, off = i & 16383;
    const float* s = (slot == 0) ? w0 : (slot == 1) ? w1 : (slot == 2) ? w2
                   : (slot == 3) ? w3 : w4;
    g_wtf[i] = to_tf32(s[off]);
}

// ================= CSR build ================================================
__global__ void zero_k() {
    int i = blockIdx.x * blockDim.x + threadIdx.x;
    if (i < Nn) { g_cnt[i] = 0; g_lsum[i] = 0.f; }
    if (i < NB_SCAN) g_scanstate[i] = 0u;
}
__global__ void hist_k(const int* __restrict__ ei, const float* __restrict__ ea) {
    int e = blockIdx.x * blockDim.x + threadIdx.x;
    if (e < Ee) {
        int dst = ei[Ee + e];
        atomicAdd(&g_cnt[dst], 1);
        atomicAdd(&g_lsum[dst], ea[e]);
    }
}
// single-pass decoupled-lookback scan + rowptr/lattr finalize
__global__ void scan_k() {
    __shared__ int s[256];
    __shared__ int s_prefix;
    const int b = blockIdx.x, t = threadIdx.x;
    const int i = b * 256 + t;
    int v = (i < Nn) ? g_cnt[i] : 0;
    s[t] = v; __syncthreads();
#pragma unroll
    for (int off = 1; off < 256; off <<= 1) {
        int add = (t >= off) ? s[t - off] : 0;
        __syncthreads();
        s[t] += add;
        __syncthreads();
    }
    const int total = s[255];
    if (t == 0) {
        if (b == 0) {
            g_scanstate[0] = (unsigned)total | PREFIX_READY;
            s_prefix = 0;
        } else {
            g_scanstate[b] = (unsigned)total | AGG_READY;
            int exc = 0;
            int j = b - 1;
            while (j >= 0) {
                unsigned st = g_scanstate[j];
                if (st & PREFIX_READY) { exc += (int)(st & VAL_MASK); break; }
                if (st & AGG_READY)    { exc += (int)(st & VAL_MASK); j--; }
            }
            g_scanstate[b] = (unsigned)(exc + total) | PREFIX_READY;
            s_prefix = exc;
        }
    }
    __syncthreads();
    if (i < Nn) {
        int beg = s_prefix + s[t] - v;
        g_beg[i] = beg;
        g_wp[i] = beg;
        g_lattr[i] = (v > 0) ? g_lsum[i] / (float)v : 0.f;
    }
}
__global__ void scatter_k(const int* __restrict__ ei, const float* __restrict__ ea) {
    int e = blockIdx.x * blockDim.x + threadIdx.x;
    if (e < Ee) {
        int dst = ei[Ee + e];
        int pos = atomicAdd(&g_wp[dst], 1);
        g_edge[pos] = make_int2(ei[e], __float_as_int(ea[e]));
    }
}

// ================= tf32 tensor-core GEMM ====================================
#define ASTRIDE 36
#define BSTRIDE 136
#define ASZ (128 * ASTRIDE)
#define BSZ (32 * BSTRIDE)
#define GEMM_SMEM ((ASZ + BSZ) * 2 * 4)

__global__ void __launch_bounds__(256, 2)
gemm_tc_k(const float* __restrict__ A,
          const uint32_t* __restrict__ W0, const float* __restrict__ b0, float* __restrict__ C0,
          const uint32_t* __restrict__ W1, const float* __restrict__ b1, float* __restrict__ C1,
          int M, int relu, int cvtA, int halfout) {
    const uint32_t* W  = blockIdx.y ? W1 : W0;
    const float* bias  = blockIdx.y ? b1 : b0;
    float*       Cm    = blockIdx.y ? C1 : C0;

    extern __shared__ float sm[];
    float*    As[2] = { sm, sm + ASZ };
    uint32_t* Bs[2] = { (uint32_t*)(sm + 2 * ASZ), (uint32_t*)(sm + 2 * ASZ + BSZ) };

    const int t = threadIdx.x;
    const int lane = t & 31;
    const int wid = t >> 5;
    const int warp_m = wid & 3;
    const int warp_n = wid >> 2;
    const int row0 = blockIdx.x * 128;

    const int a_row = t >> 1;
    const int a_colb = (t & 1) * 16;
    const int b_k = t >> 3;
    const int b_nb = (t & 7) * 16;
    const bool a_ok = (row0 + a_row) < M;
    const float* Arow = A + (size_t)(row0 + a_row) * 128;

    float acc[2][8][4];
#pragma unroll
    for (int i = 0; i < 2; i++)
#pragma unroll
        for (int j = 0; j < 8; j++)
#pragma unroll
            for (int k = 0; k < 4; k++) acc[i][j][k] = 0.f;

#pragma unroll
    for (int q = 0; q < 4; q++) {
        cp16(&As[0][a_row * ASTRIDE + a_colb + q * 4], Arow + a_colb + q * 4, a_ok);
        cp16(&Bs[0][b_k * BSTRIDE + b_nb + q * 4], W + (size_t)b_k * 128 + b_nb + q * 4, true);
    }
    cp_commit();

    int buf = 0;
    for (int c = 0; c < 4; c++) {
        cp_wait();
        __syncthreads();
        if (c < 3) {
            int k0 = (c + 1) * 32;
            int nb = buf ^ 1;
#pragma unroll
            for (int q = 0; q < 4; q++) {
                cp16(&As[nb][a_row * ASTRIDE + a_colb + q * 4], Arow + k0 + a_colb + q * 4, a_ok);
                cp16(&Bs[nb][b_k * BSTRIDE + b_nb + q * 4], W + (size_t)(k0 + b_k) * 128 + b_nb + q * 4, true);
            }
            cp_commit();
        }
        const uint32_t* as = (const uint32_t*)As[buf];
        const uint32_t* bs = Bs[buf];
        const int ar = warp_m * 32 + (lane >> 2);
        const int ac = lane & 3;
        const int bn = warp_n * 64 + (lane >> 2);
        const int bk = lane & 3;
#pragma unroll
        for (int ks = 0; ks < 4; ks++) {
            uint32_t af[2][4];
#pragma unroll
            for (int mt = 0; mt < 2; mt++) {
                const uint32_t* ap = as + (ar + mt * 16) * ASTRIDE + ks * 8 + ac;
                uint32_t r0 = ap[0];
                uint32_t r1 = ap[8 * ASTRIDE];
                uint32_t r2 = ap[4];
                uint32_t r3 = ap[8 * ASTRIDE + 4];
                if (cvtA) {
                    r0 = to_tf32(__uint_as_float(r0));
                    r1 = to_tf32(__uint_as_float(r1));
                    r2 = to_tf32(__uint_as_float(r2));
                    r3 = to_tf32(__uint_as_float(r3));
                }
                af[mt][0] = r0; af[mt][1] = r1; af[mt][2] = r2; af[mt][3] = r3;
            }
#pragma unroll
            for (int nt = 0; nt < 8; nt++) {
                const uint32_t* bp = bs + (ks * 8 + bk) * BSTRIDE + bn + nt * 8;
                uint32_t bf0 = bp[0];
                uint32_t bf1 = bp[4 * BSTRIDE];
                mma_tf32(acc[0][nt], af[0][0], af[0][1], af[0][2], af[0][3], bf0, bf1);
                mma_tf32(acc[1][nt], af[1][0], af[1][1], af[1][2], af[1][3], bf0, bf1);
            }
        }
        __syncthreads();
        buf ^= 1;
    }

    const int crow = row0 + warp_m * 32 + (lane >> 2);
    const int ccol0 = warp_n * 64 + (lane & 3) * 2;
#pragma unroll
    for (int nt = 0; nt < 8; nt++) {
        int col = ccol0 + nt * 8;
        float bx = bias[col], by = bias[col + 1];
#pragma unroll
        for (int mt = 0; mt < 2; mt++) {
            int r0 = crow + mt * 16;
            float v0 = acc[mt][nt][0] + bx, v1 = acc[mt][nt][1] + by;
            float v2 = acc[mt][nt][2] + bx, v3 = acc[mt][nt][3] + by;
            if (relu) {
                v0 = fmaxf(v0, 0.f); v1 = fmaxf(v1, 0.f);
                v2 = fmaxf(v2, 0.f); v3 = fmaxf(v3, 0.f);
            }
            if (halfout) {
                uint32_t* Ch = (uint32_t*)Cm;
                __half2 h0 = __floats2half2_rn(v0, v1);
                __half2 h1 = __floats2half2_rn(v2, v3);
                if (r0 < M)     Ch[(size_t)r0 * 64 + (col >> 1)]       = *(uint32_t*)&h0;
                if (r0 + 8 < M) Ch[(size_t)(r0 + 8) * 64 + (col >> 1)] = *(uint32_t*)&h1;
            } else {
                if (r0 < M)     *(float2*)(Cm + (size_t)r0 * 128 + col)       = make_float2(v0, v1);
                if (r0 + 8 < M) *(float2*)(Cm + (size_t)(r0 + 8) * 128 + col) = make_float2(v2, v3);
            }
        }
    }
}

// ================= per-node fused GAT layer (4 warps / node) ================
// Block = 256 threads = 2 nodes x 4 subwarps. Each subwarp processes every
// 4th edge into private registers (half2 math); one smem combine at the end.
// Nn is even -> all blocks full -> uniform __syncthreads.
__global__ void __launch_bounds__(256)
node_agg_k(const float* __restrict__ We, const float* __restrict__ att,
           const float* __restrict__ bo) {
    const int wid  = threadIdx.x >> 5;
    const int lane = threadIdx.x & 31;
    const int nb   = wid >> 2;              // node slot in block (0/1)
    const int sw   = wid & 3;               // subwarp 0..3
    const int n    = blockIdx.x * 2 + nb;   // < Nn always (Nn even)

    __shared__ float sacc[2][4][128];
    __shared__ float sss[2][4][32];

    // per-lane constants in half2 (lane owns channels [lane*4, lane*4+4))
    float4 wf = *(const float4*)(We + lane * 4);
    float4 tf = *(const float4*)(att + lane * 4);
    const __half2 w0 = __floats2half2_rn(wf.x, wf.y);
    const __half2 w1 = __floats2half2_rn(wf.z, wf.w);
    const __half2 t0 = __floats2half2_rn(tf.x, tf.y);
    const __half2 t1 = __floats2half2_rn(tf.z, tf.w);

    uint2 ub = *(const uint2*)(g_xr16 + (size_t)n * 64 + lane * 2);
    const __half2 b0 = *(const __half2*)&ub.x;
    const __half2 b1 = *(const __half2*)&ub.y;

    float4 acc = make_float4(0.f, 0.f, 0.f, 0.f);
    float ss = 0.f;

    const int beg = g_beg[n];
    const int end = beg + g_cnt[n];

    auto process = [&](int src, float attr) {
        uint2 ua = *(const uint2*)(g_xl16 + (size_t)src * 64 + lane * 2);
        __half2 a0 = *(const __half2*)&ua.x;
        __half2 a1 = *(const __half2*)&ua.y;
        __half2 at2 = __float2half2_rn(attr);
        __half2 v0 = __hfma2(at2, w0, __hadd2(a0, b0));
        __half2 v1 = __hfma2(at2, w1, __hadd2(a1, b1));
        __half2 m0 = lrelu2(v0);
        __half2 m1 = lrelu2(v1);
        __half2 p2 = __hfma2(m1, t1, __hmul2(m0, t0));
        float2 pf = __half22float2(p2);
        float p = pf.x + pf.y;
        p += __shfl_xor_sync(0xFFFFFFFFu, p, 1);
        p += __shfl_xor_sync(0xFFFFFFFFu, p, 2);
        p += __shfl_xor_sync(0xFFFFFFFFu, p, 4);
        float e = __expf(p);
        float2 f0 = __half22float2(a0);
        float2 f1 = __half22float2(a1);
        acc.x = fmaf(e, f0.x, acc.x);
        acc.y = fmaf(e, f0.y, acc.y);
        acc.z = fmaf(e, f1.x, acc.z);
        acc.w = fmaf(e, f1.y, acc.w);
        ss += e;
    };

    if (sw == 0) process(n, g_lattr[n]);           // self loop
    for (int j = beg + sw; j < end; j += 4) {
        int2 ed = g_edge[j];
        process(ed.x, __int_as_float(ed.y));
    }

    *(float4*)&sacc[nb][sw][lane * 4] = acc;
    sss[nb][sw][lane] = ss;
    __syncthreads();

    if (sw == 0) {
        float4 a0 = *(const float4*)&sacc[nb][0][lane * 4];
        float4 a1 = *(const float4*)&sacc[nb][1][lane * 4];
        float4 a2 = *(const float4*)&sacc[nb][2][lane * 4];
        float4 a3 = *(const float4*)&sacc[nb][3][lane * 4];
        float st = sss[nb][0][lane] + sss[nb][1][lane]
                 + sss[nb][2][lane] + sss[nb][3][lane];
        float inv = 1.f / (st + 1e-16f);
        float4 bo4 = *(const float4*)(bo + lane * 4);
        uint4 o;
        o.x = to_tf32(fmaxf((a0.x + a1.x + a2.x + a3.x) * inv + bo4.x, 0.f));
        o.y = to_tf32(fmaxf((a0.y + a1.y + a2.y + a3.y) * inv + bo4.y, 0.f));
        o.z = to_tf32(fmaxf((a0.z + a1.z + a2.z + a3.z) * inv + bo4.z, 0.f));
        o.w = to_tf32(fmaxf((a0.w + a1.w + a2.w + a3.w) * inv + bo4.w, 0.f));
        *(uint4*)(g_h + (size_t)n * 128 + lane * 4) = o;
    }
}

// ================= launch ===================================================
extern "C" void kernel_launch(void* const* d_in, const int* in_sizes, int n_in,
                              void* d_out, int out_size) {
    const float* x    = (const float*)d_in[0];
    const int*   ei   = (const int*)  d_in[1];
    const float* ea   = (const float*)d_in[2];
    const float* Wl1  = (const float*)d_in[3];
    const float* bl1  = (const float*)d_in[4];
    const float* Wr1  = (const float*)d_in[5];
    const float* br1  = (const float*)d_in[6];
    const float* We1  = (const float*)d_in[7];
    const float* att1 = (const float*)d_in[8];
    const float* bo1  = (const float*)d_in[9];
    const float* Wl2  = (const float*)d_in[10];
    const float* bl2  = (const float*)d_in[11];
    const float* Wr2  = (const float*)d_in[12];
    const float* br2  = (const float*)d_in[13];
    const float* We2  = (const float*)d_in[14];
    const float* att2 = (const float*)d_in[15];
    const float* bo2  = (const float*)d_in[16];
    const float* Wlin = (const float*)d_in[17];
    const float* blin = (const float*)d_in[18];
    float* out = (float*)d_out;

    float *pxl16, *pxr16, *ph;
    uint32_t* pw;
    cudaGetSymbolAddress((void**)&pxl16, g_xl16);
    cudaGetSymbolAddress((void**)&pxr16, g_xr16);
    cudaGetSymbolAddress((void**)&ph,    g_h);
    cudaGetSymbolAddress((void**)&pw,    g_wtf);

    static cudaStream_t s1;
    static cudaEvent_t evFork, evCSR;
    static int inited = 0;
    if (!inited) {
        cudaFuncSetAttribute(gemm_tc_k, cudaFuncAttributeMaxDynamicSharedMemorySize, GEMM_SMEM);
        cudaStreamCreateWithFlags(&s1, cudaStreamNonBlocking);
        cudaEventCreateWithFlags(&evFork, cudaEventDisableTiming);
        cudaEventCreateWithFlags(&evCSR, cudaEventDisableTiming);
        inited = 1;
    }

    const int TB = 256;
    const int gb_n  = (Nn + TB - 1) / TB;
    const int gb_e  = (Ee + TB - 1) / TB;
    const int gb_w  = (5 * 16384 + TB - 1) / TB;
    const int gb_gemm = (Nn + 127) / 128;
    const int gb_node = Nn / 2;                    // 2 nodes per 256-thr block
    dim3 grid2(gb_gemm, 2), grid1(gb_gemm, 1);

    const uint32_t* wl1 = pw + 0 * 16384;
    const uint32_t* wr1 = pw + 1 * 16384;
    const uint32_t* wl2 = pw + 2 * 16384;
    const uint32_t* wr2 = pw + 3 * 16384;
    const uint32_t* wli = pw + 4 * 16384;

    // ---- fork: CSR chain on s1, concurrent with cvtW+GEMM1 on s0 ----
    cudaEventRecord(evFork, 0);
    cudaStreamWaitEvent(s1, evFork, 0);

    zero_k<<<gb_n, TB, 0, s1>>>();
    hist_k<<<gb_e, TB, 0, s1>>>(ei, ea);
    scan_k<<<NB_SCAN, 256, 0, s1>>>();
    scatter_k<<<gb_e, TB, 0, s1>>>(ei, ea);
    cudaEventRecord(evCSR, s1);

    // s0: weight preconvert + layer-1 GEMMs
    cvtW_k<<<gb_w, TB>>>(Wl1, Wr1, Wl2, Wr2, Wlin);
    gemm_tc_k<<<grid2, TB, GEMM_SMEM>>>(x, wl1, bl1, pxl16, wr1, br1, pxr16, Nn, 0, 1, 1);

    // join: node_agg needs both GEMM1 outputs and the CSR
    cudaStreamWaitEvent(0, evCSR, 0);
    node_agg_k<<<gb_node, TB>>>(We1, att1, bo1);

    // ---- layer 2 ----
    gemm_tc_k<<<grid2, TB, GEMM_SMEM>>>(ph, wl2, bl2, pxl16, wr2, br2, pxr16, Nn, 0, 0, 1);
    node_agg_k<<<gb_node, TB>>>(We2, att2, bo2);

    // ---- final linear + relu -> d_out (fp32 out) ----
    gemm_tc_k<<<grid1, TB, GEMM_SMEM>>>(ph, wli, blin, out, wli, blin, out, Nn, 1, 0, 0);
}

// round 12
// speedup vs baseline: 1.0732x; 1.0732x over previous
#include <cuda_runtime.h>
#include <cuda_fp16.h>
#include <cstdint>

#define Nn 50000
#define Ee 800000
#define NEG 0.2f
#define NB_SCAN ((Nn + 255) / 256)
#define EQ (Ee / 4)

// ---------------- scratch (device globals; no runtime allocation) ----------
__device__ uint32_t g_xl16[(size_t)Nn * 64];   // xl in half2 pairs
__device__ uint32_t g_xr16[(size_t)Nn * 64];   // xr in half2 pairs
__device__ float    g_h[(size_t)Nn * 128];
__device__ float    g_lsum[Nn];
__device__ float    g_lattr[Nn];
__device__ int      g_cnt[Nn];
__device__ int      g_beg[Nn];
__device__ int      g_wp[Nn];
__device__ volatile unsigned g_scanstate[NB_SCAN];
__device__ int2     g_edge[Ee];                // (src, attr-bits)
__device__ uint32_t g_wtf[5 * 128 * 128];      // weights pre-converted to tf32 bits

#define AGG_READY    0x40000000u
#define PREFIX_READY 0x80000000u
#define VAL_MASK     0x3FFFFFFFu

// ---------------- helpers ---------------------------------------------------
__device__ __forceinline__ uint32_t to_tf32(float f) {
    uint32_t u;
    asm("cvt.rna.tf32.f32 %0, %1;" : "=r"(u) : "f"(f));
    return u;
}
__device__ __forceinline__ void cp16(void* s, const void* g, bool pred) {
    unsigned sa = (unsigned)__cvta_generic_to_shared(s);
    int sz = pred ? 16 : 0;
    asm volatile("cp.async.cg.shared.global [%0], [%1], 16, %2;\n"
                 :: "r"(sa), "l"(g), "r"(sz));
}
__device__ __forceinline__ void cp_commit() { asm volatile("cp.async.commit_group;\n"); }
__device__ __forceinline__ void cp_wait()   { asm volatile("cp.async.wait_group 0;\n"); }

__device__ __forceinline__ void mma_tf32(float c[4], uint32_t a0, uint32_t a1,
                                         uint32_t a2, uint32_t a3,
                                         uint32_t b0, uint32_t b1) {
    asm volatile(
        "mma.sync.aligned.m16n8k8.row.col.f32.tf32.tf32.f32 "
        "{%0,%1,%2,%3}, {%4,%5,%6,%7}, {%8,%9}, {%0,%1,%2,%3};\n"
        : "+f"(c[0]), "+f"(c[1]), "+f"(c[2]), "+f"(c[3])
        : "r"(a0), "r"(a1), "r"(a2), "r"(a3), "r"(b0), "r"(b1));
}
__device__ __forceinline__ __half2 lrelu2(__half2 v) {
    const __half2 z = __float2half2_rn(0.f);
    const __half2 c = __float2half2_rn(NEG);
    return __hfma2(c, __hmin2(v, z), __hmax2(v, z));
}

// ================= weight preconvert (once per launch) ======================
__global__ void cvtW_k(const float* __restrict__ w0, const float* __restrict__ w1,
                       const float* __restrict__ w2, const float* __restrict__ w3,
                       const float* __restrict__ w4) {
    int i = blockIdx.x * blockDim.x + threadIdx.x;
    if (i >= 5 * 16384) return;
    int slot = i >> 14, off = i & 16383;
    const float* s = (slot == 0) ? w0 : (slot == 1) ? w1 : (slot == 2) ? w2
                   : (slot == 3) ? w3 : w4;
    g_wtf[i] = to_tf32(s[off]);
}

// ================= CSR build ================================================
__global__ void zero_k() {
    int i = blockIdx.x * blockDim.x + threadIdx.x;
    if (i < Nn) { g_cnt[i] = 0; g_lsum[i] = 0.f; }
    if (i < NB_SCAN) g_scanstate[i] = 0u;
}
// 4 independent edges per thread -> MLP=4 on atomics
__global__ void hist_k(const int* __restrict__ ei, const float* __restrict__ ea) {
    int t = blockIdx.x * blockDim.x + threadIdx.x;
    if (t >= EQ) return;
    int d0 = ei[Ee + t];
    int d1 = ei[Ee + t + EQ];
    int d2 = ei[Ee + t + 2 * EQ];
    int d3 = ei[Ee + t + 3 * EQ];
    float a0 = ea[t];
    float a1 = ea[t + EQ];
    float a2 = ea[t + 2 * EQ];
    float a3 = ea[t + 3 * EQ];
    atomicAdd(&g_cnt[d0], 1);
    atomicAdd(&g_cnt[d1], 1);
    atomicAdd(&g_cnt[d2], 1);
    atomicAdd(&g_cnt[d3], 1);
    atomicAdd(&g_lsum[d0], a0);
    atomicAdd(&g_lsum[d1], a1);
    atomicAdd(&g_lsum[d2], a2);
    atomicAdd(&g_lsum[d3], a3);
}
// single-pass decoupled-lookback scan + rowptr/lattr finalize
__global__ void scan_k() {
    __shared__ int s[256];
    __shared__ int s_prefix;
    const int b = blockIdx.x, t = threadIdx.x;
    const int i = b * 256 + t;
    int v = (i < Nn) ? g_cnt[i] : 0;
    s[t] = v; __syncthreads();
#pragma unroll
    for (int off = 1; off < 256; off <<= 1) {
        int add = (t >= off) ? s[t - off] : 0;
        __syncthreads();
        s[t] += add;
        __syncthreads();
    }
    const int total = s[255];
    if (t == 0) {
        if (b == 0) {
            g_scanstate[0] = (unsigned)total | PREFIX_READY;
            s_prefix = 0;
        } else {
            g_scanstate[b] = (unsigned)total | AGG_READY;
            int exc = 0;
            int j = b - 1;
            while (j >= 0) {
                unsigned st = g_scanstate[j];
                if (st & PREFIX_READY) { exc += (int)(st & VAL_MASK); break; }
                if (st & AGG_READY)    { exc += (int)(st & VAL_MASK); j--; }
            }
            g_scanstate[b] = (unsigned)(exc + total) | PREFIX_READY;
            s_prefix = exc;
        }
    }
    __syncthreads();
    if (i < Nn) {
        int beg = s_prefix + s[t] - v;
        g_beg[i] = beg;
        g_wp[i] = beg;
        g_lattr[i] = (v > 0) ? g_lsum[i] / (float)v : 0.f;
    }
}
// 4 independent edges per thread -> MLP=4 on wp atomics + stores
__global__ void scatter_k(const int* __restrict__ ei, const float* __restrict__ ea) {
    int t = blockIdx.x * blockDim.x + threadIdx.x;
    if (t >= EQ) return;
    int s0 = ei[t];
    int s1 = ei[t + EQ];
    int s2 = ei[t + 2 * EQ];
    int s3 = ei[t + 3 * EQ];
    int d0 = ei[Ee + t];
    int d1 = ei[Ee + t + EQ];
    int d2 = ei[Ee + t + 2 * EQ];
    int d3 = ei[Ee + t + 3 * EQ];
    float a0 = ea[t];
    float a1 = ea[t + EQ];
    float a2 = ea[t + 2 * EQ];
    float a3 = ea[t + 3 * EQ];
    int p0 = atomicAdd(&g_wp[d0], 1);
    int p1 = atomicAdd(&g_wp[d1], 1);
    int p2 = atomicAdd(&g_wp[d2], 1);
    int p3 = atomicAdd(&g_wp[d3], 1);
    g_edge[p0] = make_int2(s0, __float_as_int(a0));
    g_edge[p1] = make_int2(s1, __float_as_int(a1));
    g_edge[p2] = make_int2(s2, __float_as_int(a2));
    g_edge[p3] = make_int2(s3, __float_as_int(a3));
}

// ================= tf32 tensor-core GEMM ====================================
#define ASTRIDE 36
#define BSTRIDE 136
#define ASZ (128 * ASTRIDE)
#define BSZ (32 * BSTRIDE)
#define GEMM_SMEM ((ASZ + BSZ) * 2 * 4)

__global__ void __launch_bounds__(256, 2)
gemm_tc_k(const float* __restrict__ A,
          const uint32_t* __restrict__ W0, const float* __restrict__ b0, float* __restrict__ C0,
          const uint32_t* __restrict__ W1, const float* __restrict__ b1, float* __restrict__ C1,
          int M, int relu, int cvtA, int halfout) {
    const uint32_t* W  = blockIdx.y ? W1 : W0;
    const float* bias  = blockIdx.y ? b1 : b0;
    float*       Cm    = blockIdx.y ? C1 : C0;

    extern __shared__ float sm[];
    float*    As[2] = { sm, sm + ASZ };
    uint32_t* Bs[2] = { (uint32_t*)(sm + 2 * ASZ), (uint32_t*)(sm + 2 * ASZ + BSZ) };

    const int t = threadIdx.x;
    const int lane = t & 31;
    const int wid = t >> 5;
    const int warp_m = wid & 3;
    const int warp_n = wid >> 2;
    const int row0 = blockIdx.x * 128;

    const int a_row = t >> 1;
    const int a_colb = (t & 1) * 16;
    const int b_k = t >> 3;
    const int b_nb = (t & 7) * 16;
    const bool a_ok = (row0 + a_row) < M;
    const float* Arow = A + (size_t)(row0 + a_row) * 128;

    float acc[2][8][4];
#pragma unroll
    for (int i = 0; i < 2; i++)
#pragma unroll
        for (int j = 0; j < 8; j++)
#pragma unroll
            for (int k = 0; k < 4; k++) acc[i][j][k] = 0.f;

#pragma unroll
    for (int q = 0; q < 4; q++) {
        cp16(&As[0][a_row * ASTRIDE + a_colb + q * 4], Arow + a_colb + q * 4, a_ok);
        cp16(&Bs[0][b_k * BSTRIDE + b_nb + q * 4], W + (size_t)b_k * 128 + b_nb + q * 4, true);
    }
    cp_commit();

    int buf = 0;
    for (int c = 0; c < 4; c++) {
        cp_wait();
        __syncthreads();
        if (c < 3) {
            int k0 = (c + 1) * 32;
            int nb = buf ^ 1;
#pragma unroll
            for (int q = 0; q < 4; q++) {
                cp16(&As[nb][a_row * ASTRIDE + a_colb + q * 4], Arow + k0 + a_colb + q * 4, a_ok);
                cp16(&Bs[nb][b_k * BSTRIDE + b_nb + q * 4], W + (size_t)(k0 + b_k) * 128 + b_nb + q * 4, true);
            }
            cp_commit();
        }
        const uint32_t* as = (const uint32_t*)As[buf];
        const uint32_t* bs = Bs[buf];
        const int ar = warp_m * 32 + (lane >> 2);
        const int ac = lane & 3;
        const int bn = warp_n * 64 + (lane >> 2);
        const int bk = lane & 3;
#pragma unroll
        for (int ks = 0; ks < 4; ks++) {
            uint32_t af[2][4];
#pragma unroll
            for (int mt = 0; mt < 2; mt++) {
                const uint32_t* ap = as + (ar + mt * 16) * ASTRIDE + ks * 8 + ac;
                uint32_t r0 = ap[0];
                uint32_t r1 = ap[8 * ASTRIDE];
                uint32_t r2 = ap[4];
                uint32_t r3 = ap[8 * ASTRIDE + 4];
                if (cvtA) {
                    r0 = to_tf32(__uint_as_float(r0));
                    r1 = to_tf32(__uint_as_float(r1));
                    r2 = to_tf32(__uint_as_float(r2));
                    r3 = to_tf32(__uint_as_float(r3));
                }
                af[mt][0] = r0; af[mt][1] = r1; af[mt][2] = r2; af[mt][3] = r3;
            }
#pragma unroll
            for (int nt = 0; nt < 8; nt++) {
                const uint32_t* bp = bs + (ks * 8 + bk) * BSTRIDE + bn + nt * 8;
                uint32_t bf0 = bp[0];
                uint32_t bf1 = bp[4 * BSTRIDE];
                mma_tf32(acc[0][nt], af[0][0], af[0][1], af[0][2], af[0][3], bf0, bf1);
                mma_tf32(acc[1][nt], af[1][0], af[1][1], af[1][2], af[1][3], bf0, bf1);
            }
        }
        __syncthreads();
        buf ^= 1;
    }

    const int crow = row0 + warp_m * 32 + (lane >> 2);
    const int ccol0 = warp_n * 64 + (lane & 3) * 2;
#pragma unroll
    for (int nt = 0; nt < 8; nt++) {
        int col = ccol0 + nt * 8;
        float bx = bias[col], by = bias[col + 1];
#pragma unroll
        for (int mt = 0; mt < 2; mt++) {
            int r0 = crow + mt * 16;
            float v0 = acc[mt][nt][0] + bx, v1 = acc[mt][nt][1] + by;
            float v2 = acc[mt][nt][2] + bx, v3 = acc[mt][nt][3] + by;
            if (relu) {
                v0 = fmaxf(v0, 0.f); v1 = fmaxf(v1, 0.f);
                v2 = fmaxf(v2, 0.f); v3 = fmaxf(v3, 0.f);
            }
            if (halfout) {
                uint32_t* Ch = (uint32_t*)Cm;
                __half2 h0 = __floats2half2_rn(v0, v1);
                __half2 h1 = __floats2half2_rn(v2, v3);
                if (r0 < M)     Ch[(size_t)r0 * 64 + (col >> 1)]       = *(uint32_t*)&h0;
                if (r0 + 8 < M) Ch[(size_t)(r0 + 8) * 64 + (col >> 1)] = *(uint32_t*)&h1;
            } else {
                if (r0 < M)     *(float2*)(Cm + (size_t)r0 * 128 + col)       = make_float2(v0, v1);
                if (r0 + 8 < M) *(float2*)(Cm + (size_t)(r0 + 8) * 128 + col) = make_float2(v2, v3);
            }
        }
    }
}

// ================= per-node fused GAT layer (half2 + edge prefetch) =========
// One warp per dst node; next edge's descriptor+gather issued before the
// current edge is processed, overlapping gather latency with the half2 chain.
__global__ void __launch_bounds__(128)
node_agg_k(const float* __restrict__ We, const float* __restrict__ att,
           const float* __restrict__ bo) {
    int n = (blockIdx.x * blockDim.x + threadIdx.x) >> 5;
    int lane = threadIdx.x & 31;
    if (n >= Nn) return;

    float4 wf = *(const float4*)(We + lane * 4);
    float4 tf = *(const float4*)(att + lane * 4);
    const __half2 w0 = __floats2half2_rn(wf.x, wf.y);
    const __half2 w1 = __floats2half2_rn(wf.z, wf.w);
    const __half2 t0 = __floats2half2_rn(tf.x, tf.y);
    const __half2 t1 = __floats2half2_rn(tf.z, tf.w);

    uint2 ub = *(const uint2*)(g_xr16 + (size_t)n * 64 + lane * 2);
    const __half2 b0 = *(const __half2*)&ub.x;
    const __half2 b1 = *(const __half2*)&ub.y;

    float4 acc = make_float4(0.f, 0.f, 0.f, 0.f);
    float ss = 0.f;

    const int beg = g_beg[n];
    const int end = beg + g_cnt[n];

    auto process = [&](uint2 ua, float attr) {
        __half2 a0 = *(const __half2*)&ua.x;
        __half2 a1 = *(const __half2*)&ua.y;
        __half2 at2 = __float2half2_rn(attr);
        __half2 v0 = __hfma2(at2, w0, __hadd2(a0, b0));
        __half2 v1 = __hfma2(at2, w1, __hadd2(a1, b1));
        __half2 m0 = lrelu2(v0);
        __half2 m1 = lrelu2(v1);
        __half2 p2 = __hfma2(m1, t1, __hmul2(m0, t0));
        float2 pf = __half22float2(p2);
        float p = pf.x + pf.y;
        p += __shfl_xor_sync(0xFFFFFFFFu, p, 1);
        p += __shfl_xor_sync(0xFFFFFFFFu, p, 2);
        p += __shfl_xor_sync(0xFFFFFFFFu, p, 4);
        float e = __expf(p);
        float2 f0 = __half22float2(a0);
        float2 f1 = __half22float2(a1);
        acc.x = fmaf(e, f0.x, acc.x);
        acc.y = fmaf(e, f0.y, acc.y);
        acc.z = fmaf(e, f1.x, acc.z);
        acc.w = fmaf(e, f1.y, acc.w);
        ss += e;
    };

    // prime pipeline with first real edge; process self loop while it flies
    int2 ed = make_int2(0, 0);
    uint2 ua = make_uint2(0u, 0u);
    if (beg < end) {
        ed = g_edge[beg];
        ua = *(const uint2*)(g_xl16 + (size_t)ed.x * 64 + lane * 2);
    }
    {
        uint2 us = *(const uint2*)(g_xl16 + (size_t)n * 64 + lane * 2);
        process(us, g_lattr[n]);
    }
    for (int j = beg; j < end; j++) {
        int2 edn = ed;
        uint2 uan = ua;
        if (j + 1 < end) {
            edn = g_edge[j + 1];
            uan = *(const uint2*)(g_xl16 + (size_t)edn.x * 64 + lane * 2);
        }
        process(ua, __int_as_float(ed.y));
        ed = edn;
        ua = uan;
    }

    float inv = 1.f / (ss + 1e-16f);
    float4 bo4 = *(const float4*)(bo + lane * 4);
    uint4 o;
    o.x = to_tf32(fmaxf(acc.x * inv + bo4.x, 0.f));
    o.y = to_tf32(fmaxf(acc.y * inv + bo4.y, 0.f));
    o.z = to_tf32(fmaxf(acc.z * inv + bo4.z, 0.f));
    o.w = to_tf32(fmaxf(acc.w * inv + bo4.w, 0.f));
    *(uint4*)(g_h + (size_t)n * 128 + lane * 4) = o;
}

// ================= launch ===================================================
extern "C" void kernel_launch(void* const* d_in, const int* in_sizes, int n_in,
                              void* d_out, int out_size) {
    const float* x    = (const float*)d_in[0];
    const int*   ei   = (const int*)  d_in[1];
    const float* ea   = (const float*)d_in[2];
    const float* Wl1  = (const float*)d_in[3];
    const float* bl1  = (const float*)d_in[4];
    const float* Wr1  = (const float*)d_in[5];
    const float* br1  = (const float*)d_in[6];
    const float* We1  = (const float*)d_in[7];
    const float* att1 = (const float*)d_in[8];
    const float* bo1  = (const float*)d_in[9];
    const float* Wl2  = (const float*)d_in[10];
    const float* bl2  = (const float*)d_in[11];
    const float* Wr2  = (const float*)d_in[12];
    const float* br2  = (const float*)d_in[13];
    const float* We2  = (const float*)d_in[14];
    const float* att2 = (const float*)d_in[15];
    const float* bo2  = (const float*)d_in[16];
    const float* Wlin = (const float*)d_in[17];
    const float* blin = (const float*)d_in[18];
    float* out = (float*)d_out;

    float *pxl16, *pxr16, *ph;
    uint32_t* pw;
    cudaGetSymbolAddress((void**)&pxl16, g_xl16);
    cudaGetSymbolAddress((void**)&pxr16, g_xr16);
    cudaGetSymbolAddress((void**)&ph,    g_h);
    cudaGetSymbolAddress((void**)&pw,    g_wtf);

    static cudaStream_t s1;
    static cudaEvent_t evFork, evCSR;
    static int inited = 0;
    if (!inited) {
        cudaFuncSetAttribute(gemm_tc_k, cudaFuncAttributeMaxDynamicSharedMemorySize, GEMM_SMEM);
        cudaStreamCreateWithFlags(&s1, cudaStreamNonBlocking);
        cudaEventCreateWithFlags(&evFork, cudaEventDisableTiming);
        cudaEventCreateWithFlags(&evCSR, cudaEventDisableTiming);
        inited = 1;
    }

    const int TB = 256;
    const int gb_n  = (Nn + TB - 1) / TB;
    const int gb_e4 = (EQ + TB - 1) / TB;
    const int gb_w  = (5 * 16384 + TB - 1) / TB;
    const int gb_gemm = (Nn + 127) / 128;
    const int gb_node = (Nn * 32 + 127) / 128;
    dim3 grid2(gb_gemm, 2), grid1(gb_gemm, 1);

    const uint32_t* wl1 = pw + 0 * 16384;
    const uint32_t* wr1 = pw + 1 * 16384;
    const uint32_t* wl2 = pw + 2 * 16384;
    const uint32_t* wr2 = pw + 3 * 16384;
    const uint32_t* wli = pw + 4 * 16384;

    // ---- fork: CSR chain on s1, concurrent with cvtW+GEMM1 on s0 ----
    cudaEventRecord(evFork, 0);
    cudaStreamWaitEvent(s1, evFork, 0);

    zero_k<<<gb_n, TB, 0, s1>>>();
    hist_k<<<gb_e4, TB, 0, s1>>>(ei, ea);
    scan_k<<<NB_SCAN, 256, 0, s1>>>();
    scatter_k<<<gb_e4, TB, 0, s1>>>(ei, ea);
    cudaEventRecord(evCSR, s1);

    // s0: weight preconvert + layer-1 GEMMs
    cvtW_k<<<gb_w, TB>>>(Wl1, Wr1, Wl2, Wr2, Wlin);
    gemm_tc_k<<<grid2, TB, GEMM_SMEM>>>(x, wl1, bl1, pxl16, wr1, br1, pxr16, Nn, 0, 1, 1);

    // join: node_agg needs both GEMM1 outputs and the CSR
    cudaStreamWaitEvent(0, evCSR, 0);
    node_agg_k<<<gb_node, 128>>>(We1, att1, bo1);

    // ---- layer 2 ----
    gemm_tc_k<<<grid2, TB, GEMM_SMEM>>>(ph, wl2, bl2, pxl16, wr2, br2, pxr16, Nn, 0, 0, 1);
    node_agg_k<<<gb_node, 128>>>(We2, att2, bo2);

    // ---- final linear + relu -> d_out (fp32 out) ----
    gemm_tc_k<<<grid1, TB, GEMM_SMEM>>>(ph, wli, blin, out, wli, blin, out, Nn, 1, 0, 0);
}

// round 13
// speedup vs baseline: 1.3181x; 1.2282x over previous
#include <cuda_runtime.h>
#include <cuda_fp16.h>
#include <cstdint>

#define Nn 50000
#define Ee 800000
#define NEG 0.2f
#define NB_SCAN ((Nn + 255) / 256)

// ---------------- scratch (device globals; no runtime allocation) ----------
__device__ uint32_t g_x16[(size_t)Nn * 64];    // x  in half2 pairs
__device__ uint32_t g_xl16[(size_t)Nn * 64];   // xl in half2 pairs
__device__ uint32_t g_xr16[(size_t)Nn * 64];   // xr in half2 pairs
__device__ uint32_t g_h16[(size_t)Nn * 64];    // h  in half2 pairs
__device__ float    g_lsum[Nn];
__device__ float    g_lattr[Nn];
__device__ int      g_cnt[Nn];
__device__ int      g_beg[Nn];
__device__ int      g_wp[Nn];
__device__ volatile unsigned g_scanstate[NB_SCAN];
__device__ int2     g_edge[Ee];                // (src, attr-bits)
__device__ uint32_t g_wtf16[5 * 128 * 64];     // weights: transposed fp16 [n][k-pair]

#define AGG_READY    0x40000000u
#define PREFIX_READY 0x80000000u
#define VAL_MASK     0x3FFFFFFFu

// ---------------- helpers ---------------------------------------------------
__device__ __forceinline__ void cp16(void* s, const void* g, bool pred) {
    unsigned sa = (unsigned)__cvta_generic_to_shared(s);
    int sz = pred ? 16 : 0;
    asm volatile("cp.async.cg.shared.global [%0], [%1], 16, %2;\n"
                 :: "r"(sa), "l"(g), "r"(sz));
}
__device__ __forceinline__ void cp_commit() { asm volatile("cp.async.commit_group;\n"); }
__device__ __forceinline__ void cp_wait()   { asm volatile("cp.async.wait_group 0;\n"); }

__device__ __forceinline__ void mma_f16(float c[4], uint32_t a0, uint32_t a1,
                                        uint32_t a2, uint32_t a3,
                                        uint32_t b0, uint32_t b1) {
    asm volatile(
        "mma.sync.aligned.m16n8k16.row.col.f32.f16.f16.f32 "
        "{%0,%1,%2,%3}, {%4,%5,%6,%7}, {%8,%9}, {%0,%1,%2,%3};\n"
        : "+f"(c[0]), "+f"(c[1]), "+f"(c[2]), "+f"(c[3])
        : "r"(a0), "r"(a1), "r"(a2), "r"(a3), "r"(b0), "r"(b1));
}
__device__ __forceinline__ __half2 lrelu2(__half2 v) {
    const __half2 z = __float2half2_rn(0.f);
    const __half2 c = __float2half2_rn(NEG);
    return __hfma2(c, __hmin2(v, z), __hmax2(v, z));
}

// ================= weight preconvert: transpose + fp16 ======================
// g_wtf16[slot][n][kq] = half2( W[2kq][n], W[2kq+1][n] )
__global__ void cvtW_k(const float* __restrict__ w0, const float* __restrict__ w1,
                       const float* __restrict__ w2, const float* __restrict__ w3,
                       const float* __restrict__ w4) {
    int i = blockIdx.x * blockDim.x + threadIdx.x;
    if (i >= 5 * 8192) return;
    int slot = i >> 13, r = i & 8191;
    int n = r >> 6, kq = r & 63;
    const float* s = (slot == 0) ? w0 : (slot == 1) ? w1 : (slot == 2) ? w2
                   : (slot == 3) ? w3 : w4;
    __half2 h = __floats2half2_rn(s[(2 * kq) * 128 + n], s[(2 * kq + 1) * 128 + n]);
    g_wtf16[i] = *(uint32_t*)&h;
}

// ================= x preconvert to fp16 =====================================
__global__ void cvtX_k(const float* __restrict__ x) {
    int i = blockIdx.x * blockDim.x + threadIdx.x;
    if (i >= Nn * 64) return;
    int node = i >> 6, c = i & 63;
    __half2 h = __floats2half2_rn(x[(size_t)node * 128 + 2 * c],
                                  x[(size_t)node * 128 + 2 * c + 1]);
    g_x16[i] = *(uint32_t*)&h;
}

// ================= CSR build ================================================
__global__ void zero_k() {
    int i = blockIdx.x * blockDim.x + threadIdx.x;
    if (i < Nn) { g_cnt[i] = 0; g_lsum[i] = 0.f; }
    if (i < NB_SCAN) g_scanstate[i] = 0u;
}
__global__ void hist_k(const int* __restrict__ ei, const float* __restrict__ ea) {
    int e = blockIdx.x * blockDim.x + threadIdx.x;
    if (e < Ee) {
        int dst = ei[Ee + e];
        atomicAdd(&g_cnt[dst], 1);
        atomicAdd(&g_lsum[dst], ea[e]);
    }
}
__global__ void scan_k() {
    __shared__ int s[256];
    __shared__ int s_prefix;
    const int b = blockIdx.x, t = threadIdx.x;
    const int i = b * 256 + t;
    int v = (i < Nn) ? g_cnt[i] : 0;
    s[t] = v; __syncthreads();
#pragma unroll
    for (int off = 1; off < 256; off <<= 1) {
        int add = (t >= off) ? s[t - off] : 0;
        __syncthreads();
        s[t] += add;
        __syncthreads();
    }
    const int total = s[255];
    if (t == 0) {
        if (b == 0) {
            g_scanstate[0] = (unsigned)total | PREFIX_READY;
            s_prefix = 0;
        } else {
            g_scanstate[b] = (unsigned)total | AGG_READY;
            int exc = 0;
            int j = b - 1;
            while (j >= 0) {
                unsigned st = g_scanstate[j];
                if (st & PREFIX_READY) { exc += (int)(st & VAL_MASK); break; }
                if (st & AGG_READY)    { exc += (int)(st & VAL_MASK); j--; }
            }
            g_scanstate[b] = (unsigned)(exc + total) | PREFIX_READY;
            s_prefix = exc;
        }
    }
    __syncthreads();
    if (i < Nn) {
        int beg = s_prefix + s[t] - v;
        g_beg[i] = beg;
        g_wp[i] = beg;
        g_lattr[i] = (v > 0) ? g_lsum[i] / (float)v : 0.f;
    }
}
__global__ void scatter_k(const int* __restrict__ ei, const float* __restrict__ ea) {
    int e = blockIdx.x * blockDim.x + threadIdx.x;
    if (e < Ee) {
        int dst = ei[Ee + e];
        int pos = atomicAdd(&g_wp[dst], 1);
        g_edge[pos] = make_int2(ei[e], __float_as_int(ea[e]));
    }
}

// ================= fp16 tensor-core GEMM (m16n8k16) =========================
// C[M][128] = A[M][128] @ W[128][128] + bias. A fp16 half2-packed [M][64];
// W pre-transposed fp16 [128 n][64 k-pairs]. One-shot 128x128 tiles.
#define TSTRIDE 68                          // uint32 stride (conflict-free)
#define GEMM_SMEM (2 * 128 * TSTRIDE * 4)

__global__ void __launch_bounds__(256, 2)
gemm_fp16_k(const uint32_t* __restrict__ A,
            const uint32_t* __restrict__ W0, const float* __restrict__ b0, void* __restrict__ C0,
            const uint32_t* __restrict__ W1, const float* __restrict__ b1, void* __restrict__ C1,
            int M, int relu, int halfout) {
    const uint32_t* W = blockIdx.y ? W1 : W0;
    const float* bias = blockIdx.y ? b1 : b0;
    void*        Cm   = blockIdx.y ? C1 : C0;

    extern __shared__ uint32_t smu[];
    uint32_t* As = smu;
    uint32_t* Bs = smu + 128 * TSTRIDE;

    const int t = threadIdx.x;
    const int lane = t & 31;
    const int wid = t >> 5;
    const int warp_m = wid & 3;
    const int warp_n = wid >> 2;
    const int row0 = blockIdx.x * 128;

    // one-shot global -> smem (A tile 32KB, B tile 32KB)
    const int lrow = t >> 1;
    const int lcol = (t & 1) * 32;
    const bool a_ok = (row0 + lrow) < M;
#pragma unroll
    for (int q = 0; q < 8; q++) {
        cp16(&As[lrow * TSTRIDE + lcol + q * 4],
             A + (size_t)(row0 + lrow) * 64 + lcol + q * 4, a_ok);
        cp16(&Bs[lrow * TSTRIDE + lcol + q * 4],
             W + (size_t)lrow * 64 + lcol + q * 4, true);
    }
    cp_commit();

    float acc[2][8][4];
#pragma unroll
    for (int i = 0; i < 2; i++)
#pragma unroll
        for (int j = 0; j < 8; j++)
#pragma unroll
            for (int k = 0; k < 4; k++) acc[i][j][k] = 0.f;

    cp_wait();
    __syncthreads();

    const int g = lane >> 2;
    const int tid4 = lane & 3;
    const int ar = warp_m * 32 + g;
    const int bn = warp_n * 64 + g;

#pragma unroll
    for (int ks = 0; ks < 8; ks++) {
        uint32_t a[2][4];
#pragma unroll
        for (int mt = 0; mt < 2; mt++) {
            const uint32_t* ap = As + (ar + mt * 16) * TSTRIDE + ks * 8 + tid4;
            a[mt][0] = ap[0];
            a[mt][1] = ap[8 * TSTRIDE];
            a[mt][2] = ap[4];
            a[mt][3] = ap[8 * TSTRIDE + 4];
        }
#pragma unroll
        for (int nt = 0; nt < 8; nt++) {
            const uint32_t* bp = Bs + (bn + nt * 8) * TSTRIDE + ks * 8 + tid4;
            uint32_t bf0 = bp[0];
            uint32_t bf1 = bp[4];
            mma_f16(acc[0][nt], a[0][0], a[0][1], a[0][2], a[0][3], bf0, bf1);
            mma_f16(acc[1][nt], a[1][0], a[1][1], a[1][2], a[1][3], bf0, bf1);
        }
    }

    const int crow = row0 + warp_m * 32 + g;
    const int ccol0 = warp_n * 64 + tid4 * 2;
#pragma unroll
    for (int nt = 0; nt < 8; nt++) {
        int col = ccol0 + nt * 8;
        float bx = bias[col], by = bias[col + 1];
#pragma unroll
        for (int mt = 0; mt < 2; mt++) {
            int r0 = crow + mt * 16;
            float v0 = acc[mt][nt][0] + bx, v1 = acc[mt][nt][1] + by;
            float v2 = acc[mt][nt][2] + bx, v3 = acc[mt][nt][3] + by;
            if (relu) {
                v0 = fmaxf(v0, 0.f); v1 = fmaxf(v1, 0.f);
                v2 = fmaxf(v2, 0.f); v3 = fmaxf(v3, 0.f);
            }
            if (halfout) {
                uint32_t* Ch = (uint32_t*)Cm;
                __half2 h0 = __floats2half2_rn(v0, v1);
                __half2 h1 = __floats2half2_rn(v2, v3);
                if (r0 < M)     Ch[(size_t)r0 * 64 + (col >> 1)]       = *(uint32_t*)&h0;
                if (r0 + 8 < M) Ch[(size_t)(r0 + 8) * 64 + (col >> 1)] = *(uint32_t*)&h1;
            } else {
                float* Cf = (float*)Cm;
                if (r0 < M)     *(float2*)(Cf + (size_t)r0 * 128 + col)       = make_float2(v0, v1);
                if (r0 + 8 < M) *(float2*)(Cf + (size_t)(r0 + 8) * 128 + col) = make_float2(v2, v3);
            }
        }
    }
}

// ================= per-node fused GAT layer (half2, R10 form) ===============
__global__ void __launch_bounds__(128)
node_agg_k(const float* __restrict__ We, const float* __restrict__ att,
           const float* __restrict__ bo) {
    int n = (blockIdx.x * blockDim.x + threadIdx.x) >> 5;
    int lane = threadIdx.x & 31;
    if (n >= Nn) return;

    float4 wf = *(const float4*)(We + lane * 4);
    float4 tf = *(const float4*)(att + lane * 4);
    const __half2 w0 = __floats2half2_rn(wf.x, wf.y);
    const __half2 w1 = __floats2half2_rn(wf.z, wf.w);
    const __half2 t0 = __floats2half2_rn(tf.x, tf.y);
    const __half2 t1 = __floats2half2_rn(tf.z, tf.w);

    uint2 ub = *(const uint2*)(g_xr16 + (size_t)n * 64 + lane * 2);
    const __half2 b0 = *(const __half2*)&ub.x;
    const __half2 b1 = *(const __half2*)&ub.y;

    float4 acc = make_float4(0.f, 0.f, 0.f, 0.f);
    float ss = 0.f;

    const int beg = g_beg[n];
    const int end = beg + g_cnt[n];

    auto process = [&](int src, float attr) {
        uint2 ua = *(const uint2*)(g_xl16 + (size_t)src * 64 + lane * 2);
        __half2 a0 = *(const __half2*)&ua.x;
        __half2 a1 = *(const __half2*)&ua.y;
        __half2 at2 = __float2half2_rn(attr);
        __half2 v0 = __hfma2(at2, w0, __hadd2(a0, b0));
        __half2 v1 = __hfma2(at2, w1, __hadd2(a1, b1));
        __half2 m0 = lrelu2(v0);
        __half2 m1 = lrelu2(v1);
        __half2 p2 = __hfma2(m1, t1, __hmul2(m0, t0));
        float2 pf = __half22float2(p2);
        float p = pf.x + pf.y;
        p += __shfl_xor_sync(0xFFFFFFFFu, p, 1);
        p += __shfl_xor_sync(0xFFFFFFFFu, p, 2);
        p += __shfl_xor_sync(0xFFFFFFFFu, p, 4);
        float e = __expf(p);
        float2 f0 = __half22float2(a0);
        float2 f1 = __half22float2(a1);
        acc.x = fmaf(e, f0.x, acc.x);
        acc.y = fmaf(e, f0.y, acc.y);
        acc.z = fmaf(e, f1.x, acc.z);
        acc.w = fmaf(e, f1.y, acc.w);
        ss += e;
    };

    process(n, g_lattr[n]);          // self loop
    for (int j = beg; j < end; j++) {
        int2 ed = g_edge[j];
        process(ed.x, __int_as_float(ed.y));
    }

    float inv = 1.f / (ss + 1e-16f);
    float4 bo4 = *(const float4*)(bo + lane * 4);
    __half2 h01 = __floats2half2_rn(fmaxf(acc.x * inv + bo4.x, 0.f),
                                    fmaxf(acc.y * inv + bo4.y, 0.f));
    __half2 h23 = __floats2half2_rn(fmaxf(acc.z * inv + bo4.z, 0.f),
                                    fmaxf(acc.w * inv + bo4.w, 0.f));
    uint2 o = make_uint2(*(uint32_t*)&h01, *(uint32_t*)&h23);
    *(uint2*)(g_h16 + (size_t)n * 64 + lane * 2) = o;
}

// ================= launch ===================================================
extern "C" void kernel_launch(void* const* d_in, const int* in_sizes, int n_in,
                              void* d_out, int out_size) {
    const float* x    = (const float*)d_in[0];
    const int*   ei   = (const int*)  d_in[1];
    const float* ea   = (const float*)d_in[2];
    const float* Wl1  = (const float*)d_in[3];
    const float* bl1  = (const float*)d_in[4];
    const float* Wr1  = (const float*)d_in[5];
    const float* br1  = (const float*)d_in[6];
    const float* We1  = (const float*)d_in[7];
    const float* att1 = (const float*)d_in[8];
    const float* bo1  = (const float*)d_in[9];
    const float* Wl2  = (const float*)d_in[10];
    const float* bl2  = (const float*)d_in[11];
    const float* Wr2  = (const float*)d_in[12];
    const float* br2  = (const float*)d_in[13];
    const float* We2  = (const float*)d_in[14];
    const float* att2 = (const float*)d_in[15];
    const float* bo2  = (const float*)d_in[16];
    const float* Wlin = (const float*)d_in[17];
    const float* blin = (const float*)d_in[18];
    float* out = (float*)d_out;

    uint32_t *px16, *pxl16, *pxr16, *ph16, *pw;
    cudaGetSymbolAddress((void**)&px16,  g_x16);
    cudaGetSymbolAddress((void**)&pxl16, g_xl16);
    cudaGetSymbolAddress((void**)&pxr16, g_xr16);
    cudaGetSymbolAddress((void**)&ph16,  g_h16);
    cudaGetSymbolAddress((void**)&pw,    g_wtf16);

    static cudaStream_t s1;
    static cudaEvent_t evFork, evCSR;
    static int inited = 0;
    if (!inited) {
        cudaFuncSetAttribute(gemm_fp16_k, cudaFuncAttributeMaxDynamicSharedMemorySize, GEMM_SMEM);
        cudaStreamCreateWithFlags(&s1, cudaStreamNonBlocking);
        cudaEventCreateWithFlags(&evFork, cudaEventDisableTiming);
        cudaEventCreateWithFlags(&evCSR, cudaEventDisableTiming);
        inited = 1;
    }

    const int TB = 256;
    const int gb_n  = (Nn + TB - 1) / TB;
    const int gb_e  = (Ee + TB - 1) / TB;
    const int gb_w  = (5 * 8192 + TB - 1) / TB;
    const int gb_x  = (Nn * 64 + TB - 1) / TB;
    const int gb_gemm = (Nn + 127) / 128;
    const int gb_node = (Nn * 32 + 127) / 128;
    dim3 grid2(gb_gemm, 2), grid1(gb_gemm, 1);

    const uint32_t* wl1 = pw + 0 * 8192;
    const uint32_t* wr1 = pw + 1 * 8192;
    const uint32_t* wl2 = pw + 2 * 8192;
    const uint32_t* wr2 = pw + 3 * 8192;
    const uint32_t* wli = pw + 4 * 8192;

    // ---- fork: CSR chain on s1, concurrent with cvtW+cvtX+GEMM1 on s0 ----
    cudaEventRecord(evFork, 0);
    cudaStreamWaitEvent(s1, evFork, 0);

    zero_k<<<gb_n, TB, 0, s1>>>();
    hist_k<<<gb_e, TB, 0, s1>>>(ei, ea);
    scan_k<<<NB_SCAN, 256, 0, s1>>>();
    scatter_k<<<gb_e, TB, 0, s1>>>(ei, ea);
    cudaEventRecord(evCSR, s1);

    // s0: preconverts + layer-1 GEMMs
    cvtW_k<<<gb_w, TB>>>(Wl1, Wr1, Wl2, Wr2, Wlin);
    cvtX_k<<<gb_x, TB>>>(x);
    gemm_fp16_k<<<grid2, TB, GEMM_SMEM>>>(px16, wl1, bl1, pxl16, wr1, br1, pxr16, Nn, 0, 1);

    // join: node_agg needs both GEMM1 outputs and the CSR
    cudaStreamWaitEvent(0, evCSR, 0);
    node_agg_k<<<gb_node, 128>>>(We1, att1, bo1);

    // ---- layer 2 ----
    gemm_fp16_k<<<grid2, TB, GEMM_SMEM>>>(ph16, wl2, bl2, pxl16, wr2, br2, pxr16, Nn, 0, 1);
    node_agg_k<<<gb_node, 128>>>(We2, att2, bo2);

    // ---- final linear + relu -> d_out (fp32 out) ----
    gemm_fp16_k<<<grid1, TB, GEMM_SMEM>>>(ph16, wli, blin, out, wli, blin, out, Nn, 1, 0);
}